// round 2
// baseline (speedup 1.0000x reference)
#include <cuda_runtime.h>
#include <cuda_bf16.h>
#include <cstdint>

// ---------------------------------------------------------------------------
// HungarianMatcher cost matrix:
//   C[b,q,t] = 2*focal(pl[b,q,cls[t]]) + 5*L1(pb[b,q], tb[t]) - 2*giou(...)
// B=16 Q=900 C=91 T=4800 -> out [14400, 4800] fp32 (276 MB)
//
// R2 changes vs R1 (L1tex was the binding pipe at 73%):
//  - focal table stored TRANSPOSED [class][row]; per-block smem tile
//    sF[class][16 rows] -> one LDS.128 gathers F for 4 rows at once
//    (16 scalar LDS + 16 IMAD per thread -> 4 LDS.128 + 4 adds)
//  - loop k-outer / r-inner to exploit the float4 gather
//  - row data in registers via warp-uniform LDG (no smem staging for rows)
//  - target (area, cls byte-offset) packed into one float2
// ---------------------------------------------------------------------------

#define BQ_MAX   14400
#define T_MAX    4800
#define NCLS     91

__device__ float  g_Ft[(NCLS + 1) * BQ_MAX];  // transposed focal: [c][row]
__device__ float4 g_rowA[BQ_MAX];             // cxcywh * 5
__device__ float4 g_rowB[BQ_MAX];             // xyxy
__device__ float  g_rowArea[BQ_MAX];
__device__ float4 g_tgtA[T_MAX];              // cxcywh * 5
__device__ float4 g_tgtB[T_MAX];              // xyxy
__device__ float2 g_tgtM[T_MAX];              // {area, bitcast(cls*64)}

__device__ __forceinline__ float frcp_approx(float x) {
    float r;
    asm("rcp.approx.f32 %0, %1;" : "=f"(r) : "f"(x));
    return r;
}

// ------------------- prep: focal table (transposed write) -------------------
// block (32 rows, 8 classes): reads L1-reused, writes fully coalesced.
__global__ void prep_focal(const float* __restrict__ logits, int BQ, int C) {
    int row = blockIdx.x * 32 + threadIdx.x;
    int c   = blockIdx.y * 8 + threadIdx.y;
    if (row >= BQ || c >= C) return;
    float x = logits[row * C + c];
    float e = __expf(-x);
    float inv = frcp_approx(1.0f + e);
    float p = inv;          // sigmoid(x)
    float q = e * inv;      // 1 - sigmoid(x), no cancellation
    float lp = __logf(p + 1e-8f);
    float lq = __logf(q + 1e-8f);
    // 2*(pos - neg) = -0.5*q^2*log(p+eps) + 1.5*p^2*log(q+eps)
    g_Ft[(size_t)c * BQ + row] = -0.5f * q * q * lp + 1.5f * p * p * lq;
}

// ---------------------------- prep: row boxes -------------------------------
__global__ void prep_rows(const float* __restrict__ boxes, int BQ) {
    int r = blockIdx.x * blockDim.x + threadIdx.x;
    if (r >= BQ) return;
    float4 b = reinterpret_cast<const float4*>(boxes)[r];  // cx,cy,w,h
    g_rowA[r] = make_float4(5.f*b.x, 5.f*b.y, 5.f*b.z, 5.f*b.w);
    float x0 = b.x - 0.5f*b.z, y0 = b.y - 0.5f*b.w;
    float x1 = b.x + 0.5f*b.z, y1 = b.y + 0.5f*b.w;
    g_rowB[r] = make_float4(x0, y0, x1, y1);
    g_rowArea[r] = (x1 - x0) * (y1 - y0);
}

// ---------------------------- prep: tgt boxes -------------------------------
__global__ void prep_tgts(const float* __restrict__ boxes,
                          const int* __restrict__ ids, int T) {
    int t = blockIdx.x * blockDim.x + threadIdx.x;
    if (t >= T) return;
    float4 b = reinterpret_cast<const float4*>(boxes)[t];
    g_tgtA[t] = make_float4(5.f*b.x, 5.f*b.y, 5.f*b.z, 5.f*b.w);
    float x0 = b.x - 0.5f*b.z, y0 = b.y - 0.5f*b.w;
    float x1 = b.x + 0.5f*b.z, y1 = b.y + 0.5f*b.w;
    g_tgtB[t] = make_float4(x0, y0, x1, y1);
    float area = (x1 - x0) * (y1 - y0);
    int clsOff = (ids[t] - 1) * 64;   // byte offset into sF: 16 rows * 4B
    g_tgtM[t] = make_float2(area, __int_as_float(clsOff));
}

// ---------------------------- main kernel -----------------------------------
// Block 256 threads, tile = 16 rows x 256 targets.
// Thread: rr = tid>>6 -> rows rr*4..rr*4+3 ; tt = tid&63 -> 4 contig targets.
#define ROW_TILE 16
#define TGT_TILE 256

__global__ __launch_bounds__(256) void cost_kernel(float* __restrict__ out,
                                                   int BQ, int T) {
    // sF[c][rl]: 16 consecutive floats per class -> LDS.128 per (class, rr)
    __shared__ float sF[NCLS * 16 + 16];

    const int tid  = threadIdx.x;
    const int row0 = blockIdx.y * ROW_TILE;

    // stage focal tile: NCLS*4 float4s, coalesced from transposed g_Ft
    #pragma unroll 2
    for (int i = tid; i < NCLS * 4; i += 256) {
        int c = i >> 2, v = i & 3;
        float4 d = *reinterpret_cast<const float4*>(&g_Ft[(size_t)c * BQ + row0 + v * 4]);
        *reinterpret_cast<float4*>(&sF[c * 16 + v * 4]) = d;
    }
    __syncthreads();

    const int tt = tid & 63;
    const int rr = tid >> 6;
    const int j0 = blockIdx.x * TGT_TILE + tt * 4;
    if (j0 >= T) return;

    // 4 rows in registers (warp-uniform loads; all lanes share rr)
    float4 rA[4], rB[4];
    float  rAr[4];
    #pragma unroll
    for (int r = 0; r < 4; ++r) {
        int idx = row0 + (rr << 2) + r;
        rA[r]  = g_rowA[idx];
        rB[r]  = g_rowB[idx];
        rAr[r] = g_rowArea[idx];
    }

    const char* sFbase = reinterpret_cast<const char*>(sF) + (rr << 4);

    float acc[4][4];

    #pragma unroll
    for (int k = 0; k < 4; ++k) {
        const int j = j0 + k;
        const float4 ta = g_tgtA[j];
        const float4 tb = g_tgtB[j];
        const float2 m  = g_tgtM[j];
        const float  tar = m.x;

        // one LDS.128: focal cost for this class, all 4 of this thread's rows
        const float4 f4 = *reinterpret_cast<const float4*>(
            sFbase + __float_as_int(m.y));
        const float* f4p = &f4.x;

        #pragma unroll
        for (int r = 0; r < 4; ++r) {
            float f2 = f4p[r];

            // 5 * L1 (coords prescaled by 5); abs folds into FADD modifiers
            float bx = fabsf(rA[r].x - ta.x) + fabsf(rA[r].y - ta.y)
                     + fabsf(rA[r].z - ta.z) + fabsf(rA[r].w - ta.w);

            // giou, single reciprocal
            float ltx = fmaxf(rB[r].x, tb.x);
            float lty = fmaxf(rB[r].y, tb.y);
            float rbx = fminf(rB[r].z, tb.z);
            float rby = fminf(rB[r].w, tb.w);
            float iw  = fmaxf(rbx - ltx, 0.0f);
            float ih  = fmaxf(rby - lty, 0.0f);
            float inter = iw * ih;
            float uni   = rAr[r] + tar - inter;

            float ex0 = fminf(rB[r].x, tb.x);
            float ey0 = fminf(rB[r].y, tb.y);
            float ex1 = fmaxf(rB[r].z, tb.z);
            float ey1 = fmaxf(rB[r].w, tb.w);
            float enc = (ex1 - ex0) * (ey1 - ey0);

            float u = fmaxf(uni, 1e-6f);
            float e = fmaxf(enc, 1e-6f);
            float num = inter * e - (enc - uni) * u;   // giou = num/(u*e)
            float inv = frcp_approx(u * e);

            acc[r][k] = fmaf(num * inv, -2.0f, f2 + bx);
        }
    }

    #pragma unroll
    for (int r = 0; r < 4; ++r) {
        float* dst = out + (size_t)(row0 + (rr << 2) + r) * T + j0;
        asm volatile("st.global.cs.v4.f32 [%0], {%1,%2,%3,%4};"
                     :: "l"(dst), "f"(acc[r][0]), "f"(acc[r][1]),
                        "f"(acc[r][2]), "f"(acc[r][3]));
    }
}

// ---------------------------------------------------------------------------
extern "C" void kernel_launch(void* const* d_in, const int* in_sizes, int n_in,
                              void* d_out, int out_size) {
    const float* pred_logits = (const float*)d_in[0];
    const float* pred_boxes  = (const float*)d_in[1];
    const int*   tgt_ids     = (const int*)d_in[2];
    const float* tgt_boxes   = (const float*)d_in[3];
    float* out = (float*)d_out;

    const int BQ = in_sizes[1] / 4;          // 14400
    const int C  = in_sizes[0] / BQ;         // 91
    const int T  = in_sizes[2];              // 4800

    dim3 fb(32, 8);
    dim3 fg((BQ + 31) / 32, (C + 7) / 8);
    prep_focal<<<fg, fb>>>(pred_logits, BQ, C);
    prep_rows <<<(BQ + 255) / 256, 256>>>(pred_boxes, BQ);
    prep_tgts <<<(T + 255) / 256, 256>>>(tgt_boxes, tgt_ids, T);

    dim3 grid((T + TGT_TILE - 1) / TGT_TILE, (BQ + ROW_TILE - 1) / ROW_TILE);
    cost_kernel<<<grid, 256>>>(out, BQ, T);
}

// round 3
// speedup vs baseline: 1.3375x; 1.3375x over previous
#include <cuda_runtime.h>
#include <cuda_bf16.h>
#include <cstdint>

// ---------------------------------------------------------------------------
// HungarianMatcher cost matrix:
//   C[b,q,t] = 2*focal(pl[b,q,cls[t]]) + 5*L1(pb[b,q], tb[t]) - 2*giou(...)
// B=16 Q=900 C=91 T=4800 -> out [14400, 4800] fp32 (276 MB)
//
// R3: L1tex was the binding pipe (73-80%); dominant cost was strided target
// loads (16 wavefronts per vector load). Fixes:
//  - thread's 4 targets strided by 64 (lane tt contiguous) -> all target
//    loads perfectly coalesced (4 wf instead of 16)
//  - focal gather straight from L1 (row-major, 368B row -> ~3 lines/gather);
//    no shared memory, no __syncthreads
//  - scalar coalesced streaming stores (1 wf each), predicated tail
// ---------------------------------------------------------------------------

#define BQ_MAX   14400
#define T_MAX    4800
#define T_PAD    4864          // padded so strided tail loads are in-bounds
#define CP       92            // padded class stride

__device__ float  g_F[BQ_MAX * CP];     // focal cost 2*(pos-neg), row-major
__device__ float4 g_tgtA[T_PAD];        // cxcywh * 5
__device__ float4 g_tgtB[T_PAD];        // xyxy
__device__ float2 g_tgtM[T_PAD];        // {area, bitcast(cls*4 byte offset)}
__device__ float4 g_rowA[BQ_MAX];       // cxcywh * 5
__device__ float4 g_rowB[BQ_MAX];       // xyxy
__device__ float  g_rowArea[BQ_MAX];

__device__ __forceinline__ float frcp_approx(float x) {
    float r;
    asm("rcp.approx.f32 %0, %1;" : "=f"(r) : "f"(x));
    return r;
}

// ---------------------------- prep: focal table ----------------------------
__global__ void prep_focal(const float* __restrict__ logits, int BQ, int C) {
    int i = blockIdx.x * blockDim.x + threadIdx.x;
    if (i >= BQ * C) return;
    int row = i / C;
    int c   = i - row * C;
    float x = logits[i];
    float e = __expf(-x);
    float inv = frcp_approx(1.0f + e);
    float p = inv;          // sigmoid(x)
    float q = e * inv;      // 1 - sigmoid(x), no cancellation
    float lp = __logf(p + 1e-8f);
    float lq = __logf(q + 1e-8f);
    // 2*(pos - neg)
    g_F[row * CP + c] = -0.5f * q * q * lp + 1.5f * p * p * lq;
}

// ---------------------------- prep: row boxes -------------------------------
__global__ void prep_rows(const float* __restrict__ boxes, int BQ) {
    int r = blockIdx.x * blockDim.x + threadIdx.x;
    if (r >= BQ) return;
    float4 b = reinterpret_cast<const float4*>(boxes)[r];  // cx,cy,w,h
    g_rowA[r] = make_float4(5.f*b.x, 5.f*b.y, 5.f*b.z, 5.f*b.w);
    float x0 = b.x - 0.5f*b.z, y0 = b.y - 0.5f*b.w;
    float x1 = b.x + 0.5f*b.z, y1 = b.y + 0.5f*b.w;
    g_rowB[r] = make_float4(x0, y0, x1, y1);
    g_rowArea[r] = (x1 - x0) * (y1 - y0);
}

// ---------------------------- prep: tgt boxes -------------------------------
__global__ void prep_tgts(const float* __restrict__ boxes,
                          const int* __restrict__ ids, int T) {
    int t = blockIdx.x * blockDim.x + threadIdx.x;
    if (t >= T) return;
    float4 b = reinterpret_cast<const float4*>(boxes)[t];
    g_tgtA[t] = make_float4(5.f*b.x, 5.f*b.y, 5.f*b.z, 5.f*b.w);
    float x0 = b.x - 0.5f*b.z, y0 = b.y - 0.5f*b.w;
    float x1 = b.x + 0.5f*b.z, y1 = b.y + 0.5f*b.w;
    g_tgtB[t] = make_float4(x0, y0, x1, y1);
    float area = (x1 - x0) * (y1 - y0);
    g_tgtM[t] = make_float2(area, __int_as_float((ids[t] - 1) * 4));
}

// ---------------------------- main kernel -----------------------------------
// Block 256 threads = tile 16 rows x 256 targets.
//   rr = tid>>6 -> rows row0+rr*4 .. +3
//   tt = tid&63 -> targets base + tt + {0,64,128,192}  (coalesced per k)
#define ROW_TILE 16
#define TGT_TILE 256

__global__ __launch_bounds__(256) void cost_kernel(float* __restrict__ out,
                                                   int BQ, int T) {
    const int tid  = threadIdx.x;
    const int tt   = tid & 63;
    const int rr   = tid >> 6;
    const int row0 = blockIdx.y * ROW_TILE + (rr << 2);
    const int base = blockIdx.x * TGT_TILE + tt;

    // 4 strided targets in registers (all loads coalesced across lanes)
    float4 ta[4], tb[4];
    float  tar[4];
    int    coff[4];
    #pragma unroll
    for (int k = 0; k < 4; ++k) {
        const int j = base + (k << 6);
        ta[k] = g_tgtA[j];
        tb[k] = g_tgtB[j];
        float2 m = g_tgtM[j];
        tar[k]  = m.x;
        coff[k] = __float_as_int(m.y);   // cls * 4 (byte offset)
    }

    #pragma unroll
    for (int r = 0; r < 4; ++r) {
        const int row = row0 + r;
        // warp-uniform row loads (broadcast, 1 wavefront each)
        const float4 rA  = g_rowA[row];
        const float4 rB  = g_rowB[row];
        const float  rar = g_rowArea[row];
        const char*  fRow = reinterpret_cast<const char*>(g_F + row * CP);
        float* dst = out + (size_t)row * T + base;

        float acc[4];
        #pragma unroll
        for (int k = 0; k < 4; ++k) {
            // focal gather: lanes' classes span 368B -> ~3 L1 lines
            float f2 = __ldg(reinterpret_cast<const float*>(fRow + coff[k]));

            // 5 * L1 (coords prescaled by 5)
            float bx = fabsf(rA.x - ta[k].x) + fabsf(rA.y - ta[k].y)
                     + fabsf(rA.z - ta[k].z) + fabsf(rA.w - ta[k].w);

            // giou, single reciprocal
            float ltx = fmaxf(rB.x, tb[k].x);
            float lty = fmaxf(rB.y, tb[k].y);
            float rbx = fminf(rB.z, tb[k].z);
            float rby = fminf(rB.w, tb[k].w);
            float iw  = fmaxf(rbx - ltx, 0.0f);
            float ih  = fmaxf(rby - lty, 0.0f);
            float inter = iw * ih;
            float uni   = rar + tar[k] - inter;

            float ex0 = fminf(rB.x, tb[k].x);
            float ey0 = fminf(rB.y, tb[k].y);
            float ex1 = fmaxf(rB.z, tb[k].z);
            float ey1 = fmaxf(rB.w, tb[k].w);
            float enc = (ex1 - ex0) * (ey1 - ey0);

            float u = fmaxf(uni, 1e-6f);
            float e = fmaxf(enc, 1e-6f);
            float num = inter * e - (enc - uni) * u;   // giou = num/(u*e)
            float inv = frcp_approx(u * e);

            acc[k] = fmaf(num * inv, -2.0f, f2 + bx);
        }

        // coalesced streaming scalar stores (128B per warp-instruction)
        #pragma unroll
        for (int k = 0; k < 4; ++k) {
            if (base + (k << 6) < T)
                asm volatile("st.global.cs.f32 [%0], %1;"
                             :: "l"(dst + (k << 6)), "f"(acc[k]));
        }
    }
}

// ---------------------------------------------------------------------------
extern "C" void kernel_launch(void* const* d_in, const int* in_sizes, int n_in,
                              void* d_out, int out_size) {
    const float* pred_logits = (const float*)d_in[0];
    const float* pred_boxes  = (const float*)d_in[1];
    const int*   tgt_ids     = (const int*)d_in[2];
    const float* tgt_boxes   = (const float*)d_in[3];
    float* out = (float*)d_out;

    const int BQ = in_sizes[1] / 4;          // 14400
    const int C  = in_sizes[0] / BQ;         // 91
    const int T  = in_sizes[2];              // 4800

    prep_focal<<<(BQ * C + 255) / 256, 256>>>(pred_logits, BQ, C);
    prep_rows <<<(BQ + 255) / 256, 256>>>(pred_boxes, BQ);
    prep_tgts <<<(T + 255) / 256, 256>>>(tgt_boxes, tgt_ids, T);

    dim3 grid((T + TGT_TILE - 1) / TGT_TILE, (BQ + ROW_TILE - 1) / ROW_TILE);
    cost_kernel<<<grid, 256>>>(out, BQ, T);
}

// round 4
// speedup vs baseline: 1.3579x; 1.0152x over previous
#include <cuda_runtime.h>
#include <cuda_bf16.h>
#include <cstdint>

// ---------------------------------------------------------------------------
// HungarianMatcher cost matrix. B=16 Q=900 C=91 T=4800, out [14400,4800] f32.
//
// R4 (from R3: alu 50% / fma 35% / issue 69% — issue+alu balanced regime):
//  - negated storage: boxes {-x0,-y0,x1,y1}, centers -5*cxcywh -> all
//    "max then subtract" pairs become FADDs of precomputed values
//  - enclosing box via direct corners on negated data (no width identity)
//  - f32x2 packed adds for the L1 chain (operands are natural LDG.128 pairs)
//  - all hot-loop addresses are [Rbase + imm] (gather row stride 368B)
//  - tile 16 rows x 192 targets (4800 = 25*192 exact: zero predicates),
//    3 targets/thread -> fits 64 regs, __launch_bounds__(256,4) for occupancy
// ---------------------------------------------------------------------------

#define BQ_MAX   14400
#define T_MAX    4800
#define NCLS     91
#define CP       92

__device__ float  g_F[BQ_MAX * CP];     // 2*(pos-neg) focal, row-major
__device__ float4 g_tgtA[T_MAX];        // -5*cxcywh  (negated!)
__device__ float4 g_tgtB[T_MAX];        // {-x0,-y0, x1, y1}
__device__ float2 g_tgtM[T_MAX];        // {area, asfloat(cls*4)}
__device__ float4 g_rowA[BQ_MAX];       // +5*cxcywh
__device__ float4 g_rowB[BQ_MAX];       // {-x0,-y0, x1, y1}
__device__ float  g_rowArea[BQ_MAX];

__device__ __forceinline__ float frcp_approx(float x) {
    float r;
    asm("rcp.approx.f32 %0, %1;" : "=f"(r) : "f"(x));
    return r;
}

#define ADD_F32X2(out, a, b) \
    asm("add.rn.f32x2 %0, %1, %2;" : "=l"(out) : "l"(a), "l"(b))
#define UNPACK2F(lo, hi, in) \
    asm("mov.b64 {%0, %1}, %2;" : "=f"(lo), "=f"(hi) : "l"(in))

// ---------------------------- prep: focal table ----------------------------
__global__ void prep_focal(const float* __restrict__ logits, int BQ, int C) {
    int i = blockIdx.x * blockDim.x + threadIdx.x;
    if (i >= BQ * C) return;
    int row = i / C;
    int c   = i - row * C;
    float x = logits[i];
    float e = __expf(-x);
    float inv = frcp_approx(1.0f + e);
    float p = inv;          // sigmoid
    float q = e * inv;      // 1 - sigmoid, no cancellation
    float lp = __logf(p + 1e-8f);
    float lq = __logf(q + 1e-8f);
    g_F[row * CP + c] = -0.5f * q * q * lp + 1.5f * p * p * lq; // 2*(pos-neg)
}

// ---------------------------- prep: row boxes -------------------------------
__global__ void prep_rows(const float* __restrict__ boxes, int BQ) {
    int r = blockIdx.x * blockDim.x + threadIdx.x;
    if (r >= BQ) return;
    float4 b = reinterpret_cast<const float4*>(boxes)[r];  // cx,cy,w,h
    g_rowA[r] = make_float4(5.f*b.x, 5.f*b.y, 5.f*b.z, 5.f*b.w);
    float x0 = b.x - 0.5f*b.z, y0 = b.y - 0.5f*b.w;
    float x1 = b.x + 0.5f*b.z, y1 = b.y + 0.5f*b.w;
    g_rowB[r] = make_float4(-x0, -y0, x1, y1);
    g_rowArea[r] = (x1 - x0) * (y1 - y0);
}

// ---------------------------- prep: tgt boxes -------------------------------
__global__ void prep_tgts(const float* __restrict__ boxes,
                          const int* __restrict__ ids, int T) {
    int t = blockIdx.x * blockDim.x + threadIdx.x;
    if (t >= T) return;
    float4 b = reinterpret_cast<const float4*>(boxes)[t];
    g_tgtA[t] = make_float4(-5.f*b.x, -5.f*b.y, -5.f*b.z, -5.f*b.w);
    float x0 = b.x - 0.5f*b.z, y0 = b.y - 0.5f*b.w;
    float x1 = b.x + 0.5f*b.z, y1 = b.y + 0.5f*b.w;
    g_tgtB[t] = make_float4(-x0, -y0, x1, y1);
    float area = (x1 - x0) * (y1 - y0);
    g_tgtM[t] = make_float2(area, __int_as_float((ids[t] - 1) * 4));
}

// ---------------------------- main kernel -----------------------------------
// Block 256 threads = 16 rows x 192 targets (4800 = 25*192, 14400 = 900*16).
//   rr = tid>>6 -> rows row0 + rr*4 + r, r in 0..3 (warp-uniform)
//   tt = tid&63 -> targets base + tt + k*64, k in 0..2 (coalesced)
#define ROW_TILE 16
#define TGT_TILE 192

__global__ void __launch_bounds__(256, 4)
cost_kernel(float* __restrict__ out, int T) {
    const int tid  = threadIdx.x;
    const int tt   = tid & 63;
    const int rr   = tid >> 6;
    const int row0 = blockIdx.y * ROW_TILE + (rr << 2);
    const int base = blockIdx.x * TGT_TILE + tt;

    // ---- 3 targets in registers (all loads coalesced) ----
    unsigned long long taL[3], taH[3];   // packed (-5cx,-5cy) / (-5w,-5h)
    float4 tb[3];
    float  tar[3];
    const float* q[3];                   // gather base: &g_F[row0*CP + cls_k]
    {
        const char* fbase = reinterpret_cast<const char*>(g_F)
                          + (size_t)row0 * (CP * 4);
        #pragma unroll
        for (int k = 0; k < 3; ++k) {
            const int j = base + (k << 6);
            ulonglong2 a = *reinterpret_cast<const ulonglong2*>(&g_tgtA[j]);
            taL[k] = a.x;  taH[k] = a.y;
            tb[k]  = g_tgtB[j];
            float2 m = g_tgtM[j];
            tar[k] = m.x;
            q[k] = reinterpret_cast<const float*>(fbase + __float_as_int(m.y));
        }
    }

    #pragma unroll
    for (int r = 0; r < 4; ++r) {
        const int row = row0 + r;
        const ulonglong2 rA2 = *reinterpret_cast<const ulonglong2*>(&g_rowA[row]);
        const float4 rB  = g_rowB[row];
        const float  rar = g_rowArea[row];
        float* dst = out + (size_t)row * T + base;

        #pragma unroll
        for (int k = 0; k < 3; ++k) {
            // focal gather: warp-uniform row, lanes span 368B (~3 L1 lines)
            const float f2 = __ldg(q[k] + r * CP);

            // ---- 5*L1: packed adds (rA = +5c, ta = -5c), abs folds into FADD
            unsigned long long dxy, dzw;
            ADD_F32X2(dxy, rA2.x, taL[k]);
            ADD_F32X2(dzw, rA2.y, taH[k]);
            float d0, d1, d2, d3;
            UNPACK2F(d0, d1, dxy);
            UNPACK2F(d2, d3, dzw);
            float bx = (fabsf(d0) + fabsf(d1)) + (fabsf(d2) + fabsf(d3));

            // ---- giou on negated-corner data (adds instead of subs) ----
            float mltx = fminf(rB.x, tb[k].x);   // = -max(x0a,x0b)
            float mlty = fminf(rB.y, tb[k].y);
            float rbx  = fminf(rB.z, tb[k].z);   // =  min(x1a,x1b)
            float rby  = fminf(rB.w, tb[k].w);
            float sw = rbx + mltx;               // signed inter width
            float sh = rby + mlty;
            float iw = fmaxf(sw, 0.0f);
            float ih = fmaxf(sh, 0.0f);
            float inter = iw * ih;

            float mex0 = fmaxf(rB.x, tb[k].x);   // = -min(x0a,x0b)
            float mey0 = fmaxf(rB.y, tb[k].y);
            float ex1  = fmaxf(rB.z, tb[k].z);
            float ey1  = fmaxf(rB.w, tb[k].w);
            float enc = (ex1 + mex0) * (ey1 + mey0);

            float s   = rar + tar[k];
            float uni = s - inter;
            float dd  = enc - uni;
            float u = fmaxf(uni, 1e-6f);
            float e = fmaxf(enc, 1e-6f);
            float num = fmaf(dd, -u, inter * e); // inter*e - (enc-uni)*u
            float inv = frcp_approx(u * e);

            float res = fmaf(num * inv, -2.0f, f2 + bx);

            asm volatile("st.global.cs.f32 [%0], %1;"
                         :: "l"(dst + (k << 6)), "f"(res));
        }
    }
}

// ---------------------------------------------------------------------------
extern "C" void kernel_launch(void* const* d_in, const int* in_sizes, int n_in,
                              void* d_out, int out_size) {
    const float* pred_logits = (const float*)d_in[0];
    const float* pred_boxes  = (const float*)d_in[1];
    const int*   tgt_ids     = (const int*)d_in[2];
    const float* tgt_boxes   = (const float*)d_in[3];
    float* out = (float*)d_out;

    const int BQ = in_sizes[1] / 4;          // 14400
    const int C  = in_sizes[0] / BQ;         // 91
    const int T  = in_sizes[2];              // 4800

    prep_focal<<<(BQ * C + 255) / 256, 256>>>(pred_logits, BQ, C);
    prep_rows <<<(BQ + 255) / 256, 256>>>(pred_boxes, BQ);
    prep_tgts <<<(T + 255) / 256, 256>>>(tgt_boxes, tgt_ids, T);

    // T=4800 and BQ=14400 divide exactly: no tail handling needed
    dim3 grid(T / TGT_TILE, BQ / ROW_TILE);
    cost_kernel<<<grid, 256>>>(out, T);
}